// round 1
// baseline (speedup 1.0000x reference)
#include <cuda_runtime.h>
#include <cuda_bf16.h>

// Problem constants (fixed by the reference).
#define B_   16
#define S_   1024
#define H_   256
#define TOUT 4096          // S * D_MAX
#define NBIN 256

// Scratch (device globals: no allocation allowed).
__device__ int g_src[B_ * TOUT];   // frame -> phoneme index (only valid for j < len)
__device__ int g_len[B_];          // per-batch expanded length

// ---------------------------------------------------------------------------
// Kernel 1: per-batch inclusive cumsum of rounded durations, scatter the
// frame->phoneme map (inverse of searchsorted-right), emit lengths.
// Grid: B_ blocks of S_ threads.
// ---------------------------------------------------------------------------
__global__ void scan_scatter_kernel(const float* __restrict__ dur,
                                    float* __restrict__ out,
                                    long long out_size) {
    const int b = blockIdx.x;
    const int i = threadIdx.x;

    int d = (int)rintf(dur[b * S_ + i]);
    d = max(d, 0);

    // Block-wide inclusive scan (warp shuffles + warp-sum scan).
    const int lane = i & 31, warp = i >> 5;
    int v = d;
#pragma unroll
    for (int o = 1; o < 32; o <<= 1) {
        int n = __shfl_up_sync(0xffffffffu, v, o);
        if (lane >= o) v += n;
    }
    __shared__ int wsum[32];
    if (lane == 31) wsum[warp] = v;
    __syncthreads();
    if (warp == 0) {
        int w = wsum[lane];
#pragma unroll
        for (int o = 1; o < 32; o <<= 1) {
            int n = __shfl_up_sync(0xffffffffu, w, o);
            if (lane >= o) w += n;
        }
        wsum[lane] = w;
    }
    __syncthreads();
    const int csum  = v + (warp > 0 ? wsum[warp - 1] : 0);  // inclusive
    const int start = csum - d;

    // Scatter: frames [start, csum) come from phoneme i. (csum <= TOUT by construction)
    for (int j = start; j < csum; ++j)
        g_src[b * TOUT + j] = i;

    if (i == S_ - 1) {
        g_len[b] = csum;
        // Tuple output: (out[B,TOUT,H], lengths[B]) flattened; lengths at the tail.
        if (out_size >= (long long)B_ * TOUT * H_ + B_)
            out[out_size - B_ + b] = (float)csum;
    }
}

// ---------------------------------------------------------------------------
// Quantize: replicate jnp.searchsorted(linspace(vmin,vmax,256), clip(v), 'left')
// = smallest k with boundary(k) >= v, then clip to [0,255].
// Closed-form ceil with a +-1 fixup against the exact boundary formula.
// ---------------------------------------------------------------------------
__device__ __forceinline__ int qbin(float v, float vmin, float vmax,
                                    float invstep, float step) {
    v = fminf(fmaxf(v, vmin), vmax);
    int k = (int)ceilf((v - vmin) * invstep);
    k = min(max(k, 0), NBIN - 1);
    if (k > 0 && (vmin + (float)(k - 1) * step) >= v) k--;
    else if ((vmin + (float)k * step) < v) k = min(k + 1, NBIN - 1);
    return k;
}

// ---------------------------------------------------------------------------
// Kernel 2: one warp per output row (b, j). 256 floats/row = 2 float4 per lane.
// out[b,j,:] = pad ? 0 : enc[b,src,:] + ptab[pbin,:] + etab[ebin,:]
// Grid: (B_*TOUT/8) blocks of 256 threads (8 warps/rows per block).
// ---------------------------------------------------------------------------
__global__ void __launch_bounds__(256)
expand_kernel(const float4* __restrict__ enc,
              const float*  __restrict__ pitch_t,
              const float*  __restrict__ energy_t,
              const float4* __restrict__ ptab,
              const float4* __restrict__ etab,
              float4*       __restrict__ out) {
    const int w    = (blockIdx.x * blockDim.x + threadIdx.x) >> 5;  // row id
    const int lane = threadIdx.x & 31;
    if (w >= B_ * TOUT) return;

    const int b = w >> 12;          // / TOUT
    const int j = w & (TOUT - 1);

    const size_t rowo = (size_t)w * (H_ / 4);

    if (j >= g_len[b]) {
        const float4 z = make_float4(0.f, 0.f, 0.f, 0.f);
        out[rowo + lane]      = z;
        out[rowo + lane + 32] = z;
        return;
    }

    const int src = g_src[w];
    const float pv = __ldg(pitch_t + w);
    const float ev = __ldg(energy_t + w);
    const int pb = qbin(pv, 50.0f, 400.0f, 255.0f / 350.0f, 350.0f / 255.0f);
    const int eb = qbin(ev,  0.0f,   1.0f, 255.0f,          1.0f / 255.0f);

    const float4* __restrict__ er = enc  + ((size_t)(b * S_ + src)) * (H_ / 4);
    const float4* __restrict__ pr = ptab + (size_t)pb * (H_ / 4);
    const float4* __restrict__ qr = etab + (size_t)eb * (H_ / 4);

#pragma unroll
    for (int k = 0; k < 2; ++k) {
        const int c = lane + 32 * k;
        const float4 a = er[c];
        const float4 p = pr[c];
        const float4 q = qr[c];
        out[rowo + c] = make_float4(a.x + p.x + q.x,
                                    a.y + p.y + q.y,
                                    a.z + p.z + q.z,
                                    a.w + p.w + q.w);
    }
}

extern "C" void kernel_launch(void* const* d_in, const int* in_sizes, int n_in,
                              void* d_out, int out_size) {
    const float* enc      = (const float*)d_in[0];   // [B,S,H]
    const float* pitch_t  = (const float*)d_in[1];   // [B,TOUT]
    const float* energy_t = (const float*)d_in[2];   // [B,TOUT]
    const float* dur      = (const float*)d_in[3];   // [B,S]
    const float* ptab     = (const float*)d_in[4];   // [256,H]
    const float* etab     = (const float*)d_in[5];   // [256,H]
    float* out            = (float*)d_out;

    scan_scatter_kernel<<<B_, S_>>>(dur, out, (long long)out_size);

    const int rows   = B_ * TOUT;        // 65536 warps
    const int blocks = rows / 8;         // 8 warps (rows) per 256-thread block
    expand_kernel<<<blocks, 256>>>((const float4*)enc, pitch_t, energy_t,
                                   (const float4*)ptab, (const float4*)etab,
                                   (float4*)out);
}